// round 3
// baseline (speedup 1.0000x reference)
#include <cuda_runtime.h>

// Problem constants (fixed by setup_inputs)
#define BB    64      // batch_size
#define NMAX  768     // max_num_nodes
#define FF    512     // hidden dim
#define HH    16      // num heads
#define NEG_INF_F (-1000000000.0f)

#define ATTN_BLOCKS_PER_B 144
#define ATTN_BLOCKS (BB * ATTN_BLOCKS_PER_B)          // 9216
#define DENSE_ROWS  (BB * NMAX)                        // 49152
#define DENSE_BLOCKS (DENSE_ROWS / 2)                  // 24576 (2 rows/block)
#define TOTAL_BLOCKS (ATTN_BLOCKS + DENSE_BLOCKS)      // 33792

// lower_bound on sorted batch_ids
__device__ __forceinline__ int lb(const int* __restrict__ a, int N, int v) {
    int lo = 0, hi = N;
    while (lo < hi) {
        int m = (lo + hi) >> 1;
        if (__ldg(a + m) < v) lo = m + 1; else hi = m;
    }
    return lo;
}

// One fused kernel.
// Blocks [0, ATTN_BLOCKS): attn_mask fill. attn[b,h,q,j] = (j<count[b]) ? 0 : -1e9.
//   Per-b chunk = H*NMAX*(NMAX/4) = 2,359,296 float4; per-b stride 144*256 = 36864
//   = 192*192, a multiple of the row length (192 float4) -> each thread's column
//   (and float4 value) is loop-invariant: 64 pure STG.128 per thread.
// Blocks [ATTN_BLOCKS, TOTAL): dense_x gather + Dmask, 2 dense rows per block
//   (128 threads x float4 = 512 floats per row). batch_ids sorted -> graph b's
//   nodes are the contiguous slice [start[b], start[b]+count[b]).
__global__ void k_fused(const float* __restrict__ x,
                        const int* __restrict__ batch_ids,
                        int N,
                        float* __restrict__ dense,
                        float* __restrict__ dmask,
                        float4* __restrict__ attn) {
    __shared__ int s_start, s_cnt;
    const int blk = blockIdx.x;
    const int t = threadIdx.x;

    if (blk < ATTN_BLOCKS) {
        const int b = blk / ATTN_BLOCKS_PER_B;
        if (t == 0) {
            int s0 = lb(batch_ids, N, b);
            s_cnt = lb(batch_ids, N, b + 1) - s0;
        }
        __syncthreads();
        const int cnt = s_cnt;

        const long long per_b = (long long)HH * NMAX * (NMAX / 4); // 2,359,296
        const int idx0 = (blk - b * ATTN_BLOCKS_PER_B) * 256 + t;  // [0, 36864)
        const int j = (idx0 % (NMAX / 4)) * 4;                     // loop-invariant

        float4 v;
        v.x = (j + 0 < cnt) ? 0.0f : NEG_INF_F;
        v.y = (j + 1 < cnt) ? 0.0f : NEG_INF_F;
        v.z = (j + 2 < cnt) ? 0.0f : NEG_INF_F;
        v.w = (j + 3 < cnt) ? 0.0f : NEG_INF_F;

        float4* base = attn + (long long)b * per_b + idx0;
        const int stride = ATTN_BLOCKS_PER_B * 256; // 36864
        #pragma unroll 16
        for (int k = 0; k < 64; ++k) {
            base[(long long)k * stride] = v;
        }
    } else {
        const int dblk = blk - ATTN_BLOCKS;          // [0, 24576)
        const int b = dblk / (NMAX / 2);             // 384 blocks per graph
        if (t == 0) {
            int s0 = lb(batch_ids, N, b);
            s_start = s0;
            s_cnt = lb(batch_ids, N, b + 1) - s0;
        }
        __syncthreads();
        const int start = s_start;
        const int cnt = s_cnt;

        const int row = dblk * 2 + (t >> 7);         // global dense row
        const int i = row - b * NMAX;                // within-graph index
        const bool valid = (i < cnt);
        const int c = t & 127;                       // float4 lane within row

        float4 v = make_float4(0.f, 0.f, 0.f, 0.f);
        if (valid) {
            v = reinterpret_cast<const float4*>(x + (size_t)(start + i) * FF)[c];
        }
        reinterpret_cast<float4*>(dense + (size_t)row * FF)[c] = v;

        if (c == 0) dmask[row] = valid ? 1.0f : 0.0f;
    }
}

extern "C" void kernel_launch(void* const* d_in, const int* in_sizes, int n_in,
                              void* d_out, int out_size) {
    const float* x         = (const float*)d_in[0];
    const int*   batch_ids = (const int*)d_in[1];
    int N = in_sizes[1]; // 32768

    float* out   = (float*)d_out;
    float* dense = out;                                  // B*NMAX*F
    float* dmask = dense + (size_t)BB * NMAX * FF;       // B*NMAX
    float* attn  = dmask + (size_t)BB * NMAX;            // B*H*NMAX*NMAX

    k_fused<<<TOTAL_BLOCKS, 256>>>(x, batch_ids, N, dense, dmask, (float4*)attn);
}

// round 7
// speedup vs baseline: 1.0474x; 1.0474x over previous
#include <cuda_runtime.h>

// Problem constants (fixed by setup_inputs)
#define BB    64      // batch_size
#define NMAX  768     // max_num_nodes
#define FF    512     // hidden dim
#define HH    16      // num heads
#define NEG_INF_F (-1000000000.0f)

__device__ int g_starts[BB + 1];
__device__ int g_counts[BB];

// Kernel 1: boundary-detection scan over sorted batch_ids.
// starts[b] = first index with id >= b. 1 block x 1024 threads, coalesced,
// fully parallel (no dependent chains) -> ~2-3us instead of 11us.
__global__ void k_starts(const int* __restrict__ batch_ids, int N) {
    const int t = threadIdx.x;
    for (int i = t; i < N; i += 1024) {
        int cur = batch_ids[i];
        int prev = (i == 0) ? -1 : batch_ids[i - 1];
        if (cur != prev) {
            // ids jump from prev to cur at index i: starts[prev+1 .. cur] = i
            for (int b = prev + 1; b <= cur; ++b) g_starts[b] = i;
        }
        if (i == N - 1) {
            // tail: all ids beyond the last value start at N
            for (int b = cur + 1; b <= BB; ++b) g_starts[b] = N;
        }
    }
    __syncthreads();
    if (t < BB) g_counts[t] = g_starts[t + 1] - g_starts[t];
}

// Kernel 2: dense_x gather + Dmask.
// One block per dense row (B*NMAX rows), 128 threads x float4 = 512 floats.
// batch_ids sorted -> graph b's nodes are the contiguous slice
// [starts[b], starts[b]+counts[b]) -> pure gather, no atomics.
__global__ void k_dense(const float* __restrict__ x,
                        float* __restrict__ dense,
                        float* __restrict__ dmask) {
    int row = blockIdx.x;
    int b = row / NMAX;
    int i = row - b * NMAX;
    int cnt = g_counts[b];
    bool valid = (i < cnt);
    int t = threadIdx.x;

    float4 v = make_float4(0.f, 0.f, 0.f, 0.f);
    if (valid) {
        const float4* src =
            reinterpret_cast<const float4*>(x + (size_t)(g_starts[b] + i) * FF);
        v = src[t];
    }
    reinterpret_cast<float4*>(dense + (size_t)row * FF)[t] = v;

    if (t == 0) dmask[row] = valid ? 1.0f : 0.0f;
}

// Kernel 3: attn_mask fill. attn[b,h,q,j] = (j < count[b]) ? 0 : -1e9.
// Per-b chunk = H*NMAX*(NMAX/4) = 2,359,296 float4.
// grid = (144, B), 256 threads: per-b stride = 144*256 = 36864 = 192*192,
// a multiple of the row length (192 float4) -> each thread's column index
// (and thus its float4 value) is loop-invariant. 64 pure STG.128 per thread.
__global__ void k_attn(float4* __restrict__ attn) {
    const int b = blockIdx.y;
    const long long per_b = (long long)HH * NMAX * (NMAX / 4); // 2,359,296
    const int idx0 = blockIdx.x * blockDim.x + threadIdx.x;    // [0, 36864)
    const int j4 = idx0 % (NMAX / 4);                          // loop-invariant col
    const int cnt = g_counts[b];
    const int j = j4 * 4;

    float4 v;
    v.x = (j + 0 < cnt) ? 0.0f : NEG_INF_F;
    v.y = (j + 1 < cnt) ? 0.0f : NEG_INF_F;
    v.z = (j + 2 < cnt) ? 0.0f : NEG_INF_F;
    v.w = (j + 3 < cnt) ? 0.0f : NEG_INF_F;

    float4* base = attn + (long long)b * per_b + idx0;
    const int stride = 144 * 256; // 36864
    #pragma unroll 16
    for (int k = 0; k < 64; ++k) {
        base[(long long)k * stride] = v;
    }
}

extern "C" void kernel_launch(void* const* d_in, const int* in_sizes, int n_in,
                              void* d_out, int out_size) {
    const float* x         = (const float*)d_in[0];
    const int*   batch_ids = (const int*)d_in[1];
    int N = in_sizes[1]; // 32768

    float* out   = (float*)d_out;
    float* dense = out;                                  // B*NMAX*F
    float* dmask = dense + (size_t)BB * NMAX * FF;       // B*NMAX
    float* attn  = dmask + (size_t)BB * NMAX;            // B*H*NMAX*NMAX

    k_starts<<<1, 1024>>>(batch_ids, N);
    k_dense<<<BB * NMAX, 128>>>(x, dense, dmask);
    k_attn<<<dim3(144, BB), 256>>>((float4*)attn);
}

// round 12
// speedup vs baseline: 1.0970x; 1.0473x over previous
#include <cuda_runtime.h>

// Problem constants (fixed by setup_inputs)
#define BB    64      // batch_size
#define NMAX  768     // max_num_nodes
#define FF    512     // hidden dim
#define HH    16      // num heads
#define NEG_INF_F (-1000000000.0f)

__device__ int g_starts[BB + 1];

// Kernel 1: boundary detection, one thread per element. 128 blocks x 256
// threads = N exactly; every load front-batched, all SMs used ->
// ~1 DRAM round trip total (~3-4us) instead of 32 serialized ones.
__global__ void k_starts(const int* __restrict__ batch_ids, int N) {
    int i = blockIdx.x * blockDim.x + threadIdx.x;
    if (i >= N) return;
    int cur = batch_ids[i];
    int prev = (i == 0) ? -1 : batch_ids[i - 1];
    if (cur != prev) {
        // ids jump from prev to cur at index i: starts[prev+1 .. cur] = i
        for (int b = prev + 1; b <= cur; ++b) g_starts[b] = i;
    }
    if (i == N - 1) {
        // tail: all ids beyond the last value start at N
        for (int b = cur + 1; b <= BB; ++b) g_starts[b] = N;
    }
}

// Kernel 2: dense_x gather + Dmask.
// One block per dense row (B*NMAX rows), 128 threads x float4 = 512 floats.
// batch_ids sorted -> graph b's nodes are the contiguous slice
// [starts[b], starts[b+1]) -> pure gather, no atomics.
__global__ void k_dense(const float* __restrict__ x,
                        float* __restrict__ dense,
                        float* __restrict__ dmask) {
    int row = blockIdx.x;
    int b = row / NMAX;
    int i = row - b * NMAX;
    int start = g_starts[b];
    int cnt = g_starts[b + 1] - start;
    bool valid = (i < cnt);
    int t = threadIdx.x;

    float4 v = make_float4(0.f, 0.f, 0.f, 0.f);
    if (valid) {
        const float4* src =
            reinterpret_cast<const float4*>(x + (size_t)(start + i) * FF);
        v = src[t];
    }
    reinterpret_cast<float4*>(dense + (size_t)row * FF)[t] = v;

    if (t == 0) dmask[row] = valid ? 1.0f : 0.0f;
}

// Kernel 3: attn_mask fill. attn[b,h,q,j] = (j < count[b]) ? 0 : -1e9.
// Per-b chunk = H*NMAX*(NMAX/4) = 2,359,296 float4.
// grid = (144, B), 256 threads: per-b stride = 144*256 = 36864 = 192*192,
// a multiple of the row length (192 float4) -> each thread's column index
// (and thus its float4 value) is loop-invariant. 64 pure STG.128 per thread.
__global__ void k_attn(float4* __restrict__ attn) {
    const int b = blockIdx.y;
    const long long per_b = (long long)HH * NMAX * (NMAX / 4); // 2,359,296
    const int idx0 = blockIdx.x * blockDim.x + threadIdx.x;    // [0, 36864)
    const int j4 = idx0 % (NMAX / 4);                          // loop-invariant col
    const int cnt = g_starts[b + 1] - g_starts[b];
    const int j = j4 * 4;

    float4 v;
    v.x = (j + 0 < cnt) ? 0.0f : NEG_INF_F;
    v.y = (j + 1 < cnt) ? 0.0f : NEG_INF_F;
    v.z = (j + 2 < cnt) ? 0.0f : NEG_INF_F;
    v.w = (j + 3 < cnt) ? 0.0f : NEG_INF_F;

    float4* base = attn + (long long)b * per_b + idx0;
    const int stride = 144 * 256; // 36864
    #pragma unroll 16
    for (int k = 0; k < 64; ++k) {
        base[(long long)k * stride] = v;
    }
}

extern "C" void kernel_launch(void* const* d_in, const int* in_sizes, int n_in,
                              void* d_out, int out_size) {
    const float* x         = (const float*)d_in[0];
    const int*   batch_ids = (const int*)d_in[1];
    int N = in_sizes[1]; // 32768

    float* out   = (float*)d_out;
    float* dense = out;                                  // B*NMAX*F
    float* dmask = dense + (size_t)BB * NMAX * FF;       // B*NMAX
    float* attn  = dmask + (size_t)BB * NMAX;            // B*H*NMAX*NMAX

    k_starts<<<(N + 255) / 256, 256>>>(batch_ids, N);
    k_dense<<<BB * NMAX, 128>>>(x, dense, dmask);
    k_attn<<<dim3(144, BB), 256>>>((float4*)attn);
}